// round 9
// baseline (speedup 1.0000x reference)
#include <cuda_runtime.h>
#include <cuda.h>
#include <math_constants.h>
#include <cstdint>

// Problem constants (fixed by setup_inputs)
#define SLEN 4096
#define HDIM 1024
#define BATCH 8
#define KSEL 8

#define TS 128                  // s-elements per tile
#define NT (SLEN / TS)          // 32 tiles
#define ROWS 8                  // h-rows per block (one warp each)
#define STAGES 3
#define TX_BYTES (TS * ROWS * 4 * 2)   // A (4KB) + G (4KB) per stage

__device__ __align__(16) float g_pooled[BATCH * HDIM];

struct __align__(128) Smem {
    float A[STAGES][TS][ROWS];        // TMA dst: [s][h], 32B rows
    float G[STAGES][ROWS][TS];        // TMA dst: [row][s], 512B rows
    float At[ROWS][TS + 4];           // transposed A: [h][s], pad 4
    unsigned long long bar[STAGES];
};

static __device__ __forceinline__ unsigned smem_u32(const void* p) {
    return (unsigned)__cvta_generic_to_shared(p);
}
static __device__ __forceinline__ void mbar_init(unsigned addr, unsigned count) {
    asm volatile("mbarrier.init.shared.b64 [%0], %1;" :: "r"(addr), "r"(count) : "memory");
}
static __device__ __forceinline__ void mbar_expect_tx(unsigned addr, unsigned tx) {
    asm volatile("mbarrier.arrive.expect_tx.shared.b64 _, [%0], %1;" :: "r"(addr), "r"(tx) : "memory");
}
static __device__ __forceinline__ void mbar_wait(unsigned addr, unsigned parity) {
    unsigned done;
    asm volatile(
        "{\n\t.reg .pred p;\n\t"
        "mbarrier.try_wait.parity.acquire.cta.shared::cta.b64 p, [%1], %2;\n\t"
        "selp.b32 %0, 1, 0, p;\n\t}"
        : "=r"(done) : "r"(addr), "r"(parity) : "memory");
    if (!done) {
        asm volatile(
            "{\n\t.reg .pred P1;\n\t"
            "WL_%=:\n\t"
            "mbarrier.try_wait.parity.acquire.cta.shared::cta.b64 P1, [%0], %1, 0x989680;\n\t"
            "@P1 bra.uni WD_%=;\n\t"
            "bra.uni WL_%=;\n\t"
            "WD_%=:\n\t}"
            :: "r"(addr), "r"(parity) : "memory");
    }
}
static __device__ __forceinline__ void tma_load_2d(unsigned dst, const void* tm,
                                                   int cx, int cy, unsigned mbar) {
    asm volatile(
        "cp.async.bulk.tensor.2d.shared::cta.global.tile.mbarrier::complete_tx::bytes "
        "[%0], [%1, {%2, %3}], [%4];"
        :: "r"(dst), "l"(tm), "r"(cx), "r"(cy), "r"(mbar) : "memory");
}

// Insert (sc, tv) into ascending sorted top-8 arrays. Precondition: sc > s8[0].
static __device__ __forceinline__ void insert8(float sc, float tv, float (&s8)[8], float (&t8)[8]) {
    bool placed = false;
#pragma unroll
    for (int j = 0; j < 7; ++j) {
        if (!placed) {
            if (sc > s8[j + 1]) { s8[j] = s8[j + 1]; t8[j] = t8[j + 1]; }
            else { s8[j] = sc; t8[j] = tv; placed = true; }
        }
    }
    if (!placed) { s8[7] = sc; t8[7] = tv; }
}

// Warp-collective: fold all lanes' candidates (sc, tv) into the replicated top-8.
static __device__ __forceinline__ void fold(float sc, float tv, float (&s8)[8], float (&t8)[8]) {
    unsigned m = __ballot_sync(0xffffffffu, sc > s8[0]);
    while (m) {
        int src = __ffs(m) - 1;
        m &= m - 1;
        float bsc = __shfl_sync(0xffffffffu, sc, src);
        float btv = __shfl_sync(0xffffffffu, tv, src);
        if (bsc > s8[0]) insert8(bsc, btv, s8, t8);   // warp-uniform
    }
}

__global__ __launch_bounds__(256, 7)
void topk_pool_kernel(const __grid_constant__ CUtensorMap tmA,
                      const __grid_constant__ CUtensorMap tmG) {
    __shared__ Smem sm;
    const int t = threadIdx.x;
    const int blk = blockIdx.x;           // 0..1023
    const int b = blk >> 7;               // 0..7
    const int h0 = (blk & 127) << 3;      // 0..1016
    const int w = t >> 5;                 // warp = row
    const int l = t & 31;

    if (t == 0) {
#pragma unroll
        for (int s = 0; s < STAGES; ++s) mbar_init(smem_u32(&sm.bar[s]), 1);
        asm volatile("fence.proxy.async.shared::cta;" ::: "memory");
    }
    __syncthreads();

    auto issue = [&](int tile) {
        if (t == 0) {
            int st = tile % STAGES;
            unsigned mb = smem_u32(&sm.bar[st]);
            mbar_expect_tx(mb, TX_BYTES);
            tma_load_2d(smem_u32(&sm.A[st][0][0]), &tmA, h0, b * SLEN + tile * TS, mb);
            tma_load_2d(smem_u32(&sm.G[st][0][0]), &tmG, tile * TS, b * HDIM + h0, mb);
        }
    };

    issue(0);
    issue(1);

    float s8[8], t8[8];
#pragma unroll
    for (int j = 0; j < 8; ++j) { s8[j] = -CUDART_INF_F; t8[j] = 0.f; }
    const float LN2 = 0.6931471805599453f;

    // transpose mapping: thread -> (s index, 4-h group)
    const int tsi = t >> 1;               // 0..127
    const int th4 = (t & 1) * 4;          // 0 or 4

    for (int tile = 0; tile < NT; ++tile) {
        const int st = tile % STAGES;
        const unsigned ph = (unsigned)((tile / STAGES) & 1);
        // Only warp 0 polls the mbarrier; the other 7 warps sleep at the BAR
        // (no issue-slot burn). The barrier also orders compute(tile-1) for all
        // threads, preserving the buffer-liveness proof for issue(tile+2).
        if (w == 0) mbar_wait(smem_u32(&sm.bar[st]), ph);
        __syncthreads();

        // Transpose A[st][s][h] -> At[h][s]   (conflict-free both sides)
        {
            float4 v = *(const float4*)&sm.A[st][tsi][th4];
            sm.At[th4 + 0][tsi] = v.x;
            sm.At[th4 + 1][tsi] = v.y;
            sm.At[th4 + 2][tsi] = v.z;
            sm.At[th4 + 3][tsi] = v.w;
        }
        __syncthreads();

        issue(tile + 2);   // stage (tile+2)%3 == (tile-1)%3: proven drained

        // Compute: lane l owns s = 4l..4l+3 of this tile for row w.
        float4 a4 = *(const float4*)&sm.At[w][4 * l];
        float4 g4 = *(const float4*)&sm.G[st][w][4 * l];

        float tv0 = fmaxf(a4.x, 0.f), tv1 = fmaxf(a4.y, 0.f);
        float tv2 = fmaxf(a4.z, 0.f), tv3 = fmaxf(a4.w, 0.f);
        // lg2(0) = -inf -> never selected; matches reference log(relu) semantics.
        float sc0 = __fmaf_rn(__log2f(tv0), LN2, g4.x);
        float sc1 = __fmaf_rn(__log2f(tv1), LN2, g4.y);
        float sc2 = __fmaf_rn(__log2f(tv2), LN2, g4.z);
        float sc3 = __fmaf_rn(__log2f(tv3), LN2, g4.w);

        float mx = fmaxf(fmaxf(sc0, sc1), fmaxf(sc2, sc3));
        if (__ballot_sync(0xffffffffu, mx > s8[0])) {
            fold(sc0, tv0, s8, t8);
            fold(sc1, tv1, s8, t8);
            fold(sc2, tv2, s8, t8);
            fold(sc3, tv3, s8, t8);
        }
    }

    if (l == 0) {
        float sum = ((t8[0] + t8[1]) + (t8[2] + t8[3])) +
                    ((t8[4] + t8[5]) + (t8[6] + t8[7]));
        g_pooled[b * HDIM + h0 + w] = sum;
    }
}

// GEMM (R2 design, best measured): out[i][j] = tanh(b[j] + sum_h pooled[i][h]*W[j][h])
__global__ __launch_bounds__(256, 2)
void gemm_tanh_kernel(const float* __restrict__ W, const float* __restrict__ bias,
                      float* __restrict__ out) {
    __shared__ float sp[BATCH * HDIM];      // 32 KB
    __shared__ float red[4][2][BATCH];

    {
        const float4* src = (const float4*)g_pooled;
        float4* dst = (float4*)sp;
#pragma unroll
        for (int k = 0; k < (BATCH * HDIM / 4) / 256; ++k)
            dst[threadIdx.x + 256 * k] = src[threadIdx.x + 256 * k];
    }
    __syncthreads();

    const int w = threadIdx.x >> 5;
    const int lane = threadIdx.x & 31;
    const int jj = w >> 1;
    const int half = w & 1;
    const int j = blockIdx.x * 4 + jj;

    const float* wrow = W + (size_t)j * HDIM + half * 512;
    float acc[BATCH];
#pragma unroll
    for (int i = 0; i < BATCH; ++i) acc[i] = 0.f;

#pragma unroll
    for (int c = 0; c < 16; ++c) {
        int h = c * 32 + lane;
        float wv = wrow[h];
        const float* p = sp + half * 512 + h;
#pragma unroll
        for (int i = 0; i < BATCH; ++i)
            acc[i] = fmaf(p[i * HDIM], wv, acc[i]);
    }
#pragma unroll
    for (int i = 0; i < BATCH; ++i) {
#pragma unroll
        for (int off = 16; off > 0; off >>= 1)
            acc[i] += __shfl_xor_sync(0xffffffffu, acc[i], off);
    }
    if (lane == 0) {
#pragma unroll
        for (int i = 0; i < BATCH; ++i) red[jj][half][i] = acc[i];
    }
    __syncthreads();

    if (threadIdx.x < 32) {
        int i = threadIdx.x & 7;
        int jj2 = threadIdx.x >> 3;
        int jo = blockIdx.x * 4 + jj2;
        float v = red[jj2][0][i] + red[jj2][1][i] + bias[jo];
        out[i * HDIM + jo] = tanhf(v);
    }
}

// ---------------- host side ----------------

typedef CUresult (*EncodeFn)(CUtensorMap*, CUtensorMapDataType, cuuint32_t, void*,
                             const cuuint64_t*, const cuuint64_t*, const cuuint32_t*,
                             const cuuint32_t*, CUtensorMapInterleave, CUtensorMapSwizzle,
                             CUtensorMapL2promotion, CUtensorMapFloatOOBfill);

extern "C" void kernel_launch(void* const* d_in, const int* in_sizes, int n_in,
                              void* d_out, int out_size) {
    const float* hidden = (const float*)d_in[0];   // [8, 4096, 1024]
    const float* gumbel = (const float*)d_in[1];   // [8192, 4096]
    const float* W = (const float*)d_in[2];        // [1024, 1024]
    const float* bias = (const float*)d_in[3];     // [1024]
    float* out = (float*)d_out;                    // [8, 1024] float32

    static EncodeFn enc = nullptr;
    if (!enc) {
        cudaDriverEntryPointQueryResult q;
        void* fp = nullptr;
        cudaGetDriverEntryPoint("cuTensorMapEncodeTiled", &fp, cudaEnableDefault, &q);
        enc = (EncodeFn)fp;
    }

    CUtensorMap tmA, tmG;
    {   // hidden as 2D [B*S rows][H cols], box 8(h) x 128(s)
        cuuint64_t dims[2] = {HDIM, (cuuint64_t)BATCH * SLEN};
        cuuint64_t strides[1] = {HDIM * 4};
        cuuint32_t box[2] = {ROWS, TS};
        cuuint32_t es[2] = {1, 1};
        enc(&tmA, CU_TENSOR_MAP_DATA_TYPE_FLOAT32, 2, (void*)hidden,
            dims, strides, box, es,
            CU_TENSOR_MAP_INTERLEAVE_NONE, CU_TENSOR_MAP_SWIZZLE_NONE,
            CU_TENSOR_MAP_L2_PROMOTION_L2_128B, CU_TENSOR_MAP_FLOAT_OOB_FILL_NONE);
    }
    {   // gumbel as 2D [R rows][S cols], box 128(s) x 8(rows)
        cuuint64_t dims[2] = {SLEN, (cuuint64_t)BATCH * HDIM};
        cuuint64_t strides[1] = {SLEN * 4};
        cuuint32_t box[2] = {TS, ROWS};
        cuuint32_t es[2] = {1, 1};
        enc(&tmG, CU_TENSOR_MAP_DATA_TYPE_FLOAT32, 2, (void*)gumbel,
            dims, strides, box, es,
            CU_TENSOR_MAP_INTERLEAVE_NONE, CU_TENSOR_MAP_SWIZZLE_NONE,
            CU_TENSOR_MAP_L2_PROMOTION_L2_128B, CU_TENSOR_MAP_FLOAT_OOB_FILL_NONE);
    }

    topk_pool_kernel<<<BATCH * (HDIM / ROWS), 256>>>(tmA, tmG);
    gemm_tanh_kernel<<<HDIM / 4, 256>>>(W, bias, out);
}

// round 11
// speedup vs baseline: 1.0898x; 1.0898x over previous
#include <cuda_runtime.h>
#include <cuda.h>
#include <math_constants.h>
#include <cstdint>

// Problem constants (fixed by setup_inputs)
#define SLEN 4096
#define HDIM 1024
#define BATCH 8
#define KSEL 8

#define TS 128                  // s-elements per tile
#define NT (SLEN / TS)          // 32 tiles
#define ROWS 8                  // h-rows per block (one warp each)
#define STAGES 4
#define TX_BYTES (TS * ROWS * 4 * 2)   // A (4KB) + G (4KB) per stage

__device__ __align__(16) float g_pooled[BATCH * HDIM];

struct __align__(128) Smem {
    float A[STAGES][TS][ROWS];        // TMA dst: [s][h], 32B rows
    float G[STAGES][ROWS][TS];        // TMA dst: [row][s], 512B rows
    float At[ROWS][TS + 4];           // transposed A: [h][s], pad 4
    unsigned long long bar[STAGES];
};

static __device__ __forceinline__ unsigned smem_u32(const void* p) {
    return (unsigned)__cvta_generic_to_shared(p);
}
static __device__ __forceinline__ void mbar_init(unsigned addr, unsigned count) {
    asm volatile("mbarrier.init.shared.b64 [%0], %1;" :: "r"(addr), "r"(count) : "memory");
}
static __device__ __forceinline__ void mbar_expect_tx(unsigned addr, unsigned tx) {
    asm volatile("mbarrier.arrive.expect_tx.shared.b64 _, [%0], %1;" :: "r"(addr), "r"(tx) : "memory");
}
static __device__ __forceinline__ void mbar_wait(unsigned addr, unsigned parity) {
    unsigned done;
    asm volatile(
        "{\n\t.reg .pred p;\n\t"
        "mbarrier.try_wait.parity.acquire.cta.shared::cta.b64 p, [%1], %2;\n\t"
        "selp.b32 %0, 1, 0, p;\n\t}"
        : "=r"(done) : "r"(addr), "r"(parity) : "memory");
    if (!done) {
        asm volatile(
            "{\n\t.reg .pred P1;\n\t"
            "WL_%=:\n\t"
            "mbarrier.try_wait.parity.acquire.cta.shared::cta.b64 P1, [%0], %1, 0x989680;\n\t"
            "@P1 bra.uni WD_%=;\n\t"
            "bra.uni WL_%=;\n\t"
            "WD_%=:\n\t}"
            :: "r"(addr), "r"(parity) : "memory");
    }
}
static __device__ __forceinline__ void tma_load_2d(unsigned dst, const void* tm,
                                                   int cx, int cy, unsigned mbar) {
    asm volatile(
        "cp.async.bulk.tensor.2d.shared::cta.global.tile.mbarrier::complete_tx::bytes "
        "[%0], [%1, {%2, %3}], [%4];"
        :: "r"(dst), "l"(tm), "r"(cx), "r"(cy), "r"(mbar) : "memory");
}

// Insert (sc, tv) into ascending sorted top-8 arrays. Precondition: sc > s8[0].
static __device__ __forceinline__ void insert8(float sc, float tv, float (&s8)[8], float (&t8)[8]) {
    bool placed = false;
#pragma unroll
    for (int j = 0; j < 7; ++j) {
        if (!placed) {
            if (sc > s8[j + 1]) { s8[j] = s8[j + 1]; t8[j] = t8[j + 1]; }
            else { s8[j] = sc; t8[j] = tv; placed = true; }
        }
    }
    if (!placed) { s8[7] = sc; t8[7] = tv; }
}

// Warp-collective: fold all lanes' candidates (sc, tv) into the replicated top-8.
static __device__ __forceinline__ void fold(float sc, float tv, float (&s8)[8], float (&t8)[8]) {
    unsigned m = __ballot_sync(0xffffffffu, sc > s8[0]);
    while (m) {
        int src = __ffs(m) - 1;
        m &= m - 1;
        float bsc = __shfl_sync(0xffffffffu, sc, src);
        float btv = __shfl_sync(0xffffffffu, tv, src);
        if (bsc > s8[0]) insert8(bsc, btv, s8, t8);   // warp-uniform
    }
}

__global__ __launch_bounds__(256)
void topk_pool_kernel(const __grid_constant__ CUtensorMap tmA,
                      const __grid_constant__ CUtensorMap tmG) {
    __shared__ Smem sm;
    const int t = threadIdx.x;
    const int blk = blockIdx.x;           // 0..1023
    const int b = blk >> 7;               // 0..7
    const int h0 = (blk & 127) << 3;      // 0..1016
    const int w = t >> 5;                 // warp = row
    const int l = t & 31;

    if (t == 0) {
#pragma unroll
        for (int s = 0; s < STAGES; ++s) mbar_init(smem_u32(&sm.bar[s]), 1);
        asm volatile("fence.proxy.async.shared::cta;" ::: "memory");
    }
    __syncthreads();

    auto issue = [&](int tile) {
        if (t == 0) {
            int st = tile & (STAGES - 1);
            unsigned mb = smem_u32(&sm.bar[st]);
            mbar_expect_tx(mb, TX_BYTES);
            tma_load_2d(smem_u32(&sm.A[st][0][0]), &tmA, h0, b * SLEN + tile * TS, mb);
            tma_load_2d(smem_u32(&sm.G[st][0][0]), &tmG, tile * TS, b * HDIM + h0, mb);
        }
    };

    issue(0); issue(1); issue(2);

    float s8[8], t8[8];
#pragma unroll
    for (int j = 0; j < 8; ++j) { s8[j] = -CUDART_INF_F; t8[j] = 0.f; }
    const float LN2 = 0.6931471805599453f;

    // transpose mapping: thread -> (s index, 4-h group)
    const int tsi = t >> 1;               // 0..127
    const int th4 = (t & 1) * 4;          // 0 or 4

    for (int tile = 0; tile < NT; ++tile) {
        const int st = tile & (STAGES - 1);
        const unsigned ph = (unsigned)((tile / STAGES) & 1);
        // Only warp 0 polls the mbarrier; the other warps sleep at the BAR
        // (stall_barrier burns no issue slots). The BAR also orders all of
        // compute(tile-1) + transpose(tile-1), so stage (tile-1)%4 is free.
        if (w == 0) mbar_wait(smem_u32(&sm.bar[st]), ph);
        __syncthreads();

        // Refill the drained stage ASAP (before the transpose, off critical path).
        if (tile + 3 < NT) issue(tile + 3);   // stage (tile+3)%4 == (tile-1)%4

        // Transpose A[st][s][h] -> At[h][s]   (conflict-free both sides)
        {
            float4 v = *(const float4*)&sm.A[st][tsi][th4];
            sm.At[th4 + 0][tsi] = v.x;
            sm.At[th4 + 1][tsi] = v.y;
            sm.At[th4 + 2][tsi] = v.z;
            sm.At[th4 + 3][tsi] = v.w;
        }
        __syncthreads();

        // Compute: lane l owns s = 4l..4l+3 of this tile for row w.
        float4 a4 = *(const float4*)&sm.At[w][4 * l];
        float4 g4 = *(const float4*)&sm.G[st][w][4 * l];

        float tv0 = fmaxf(a4.x, 0.f), tv1 = fmaxf(a4.y, 0.f);
        float tv2 = fmaxf(a4.z, 0.f), tv3 = fmaxf(a4.w, 0.f);
        // lg2(0) = -inf -> never selected; matches reference log(relu) semantics.
        float sc0 = __fmaf_rn(__log2f(tv0), LN2, g4.x);
        float sc1 = __fmaf_rn(__log2f(tv1), LN2, g4.y);
        float sc2 = __fmaf_rn(__log2f(tv2), LN2, g4.z);
        float sc3 = __fmaf_rn(__log2f(tv3), LN2, g4.w);

        float mx = fmaxf(fmaxf(sc0, sc1), fmaxf(sc2, sc3));
        if (__ballot_sync(0xffffffffu, mx > s8[0])) {
            fold(sc0, tv0, s8, t8);
            fold(sc1, tv1, s8, t8);
            fold(sc2, tv2, s8, t8);
            fold(sc3, tv3, s8, t8);
        }
    }

    if (l == 0) {
        float sum = ((t8[0] + t8[1]) + (t8[2] + t8[3])) +
                    ((t8[4] + t8[5]) + (t8[6] + t8[7]));
        g_pooled[b * HDIM + h0 + w] = sum;
    }
}

// GEMM (R2 design, best measured): out[i][j] = tanh(b[j] + sum_h pooled[i][h]*W[j][h])
__global__ __launch_bounds__(256, 2)
void gemm_tanh_kernel(const float* __restrict__ W, const float* __restrict__ bias,
                      float* __restrict__ out) {
    __shared__ float sp[BATCH * HDIM];      // 32 KB
    __shared__ float red[4][2][BATCH];

    {
        const float4* src = (const float4*)g_pooled;
        float4* dst = (float4*)sp;
#pragma unroll
        for (int k = 0; k < (BATCH * HDIM / 4) / 256; ++k)
            dst[threadIdx.x + 256 * k] = src[threadIdx.x + 256 * k];
    }
    __syncthreads();

    const int w = threadIdx.x >> 5;
    const int lane = threadIdx.x & 31;
    const int jj = w >> 1;
    const int half = w & 1;
    const int j = blockIdx.x * 4 + jj;

    const float* wrow = W + (size_t)j * HDIM + half * 512;
    float acc[BATCH];
#pragma unroll
    for (int i = 0; i < BATCH; ++i) acc[i] = 0.f;

#pragma unroll
    for (int c = 0; c < 16; ++c) {
        int h = c * 32 + lane;
        float wv = wrow[h];
        const float* p = sp + half * 512 + h;
#pragma unroll
        for (int i = 0; i < BATCH; ++i)
            acc[i] = fmaf(p[i * HDIM], wv, acc[i]);
    }
#pragma unroll
    for (int i = 0; i < BATCH; ++i) {
#pragma unroll
        for (int off = 16; off > 0; off >>= 1)
            acc[i] += __shfl_xor_sync(0xffffffffu, acc[i], off);
    }
    if (lane == 0) {
#pragma unroll
        for (int i = 0; i < BATCH; ++i) red[jj][half][i] = acc[i];
    }
    __syncthreads();

    if (threadIdx.x < 32) {
        int i = threadIdx.x & 7;
        int jj2 = threadIdx.x >> 3;
        int jo = blockIdx.x * 4 + jj2;
        float v = red[jj2][0][i] + red[jj2][1][i] + bias[jo];
        out[i * HDIM + jo] = tanhf(v);
    }
}

// ---------------- host side ----------------

typedef CUresult (*EncodeFn)(CUtensorMap*, CUtensorMapDataType, cuuint32_t, void*,
                             const cuuint64_t*, const cuuint64_t*, const cuuint32_t*,
                             const cuuint32_t*, CUtensorMapInterleave, CUtensorMapSwizzle,
                             CUtensorMapL2promotion, CUtensorMapFloatOOBfill);

extern "C" void kernel_launch(void* const* d_in, const int* in_sizes, int n_in,
                              void* d_out, int out_size) {
    const float* hidden = (const float*)d_in[0];   // [8, 4096, 1024]
    const float* gumbel = (const float*)d_in[1];   // [8192, 4096]
    const float* W = (const float*)d_in[2];        // [1024, 1024]
    const float* bias = (const float*)d_in[3];     // [1024]
    float* out = (float*)d_out;                    // [8, 1024] float32

    static EncodeFn enc = nullptr;
    if (!enc) {
        cudaDriverEntryPointQueryResult q;
        void* fp = nullptr;
        cudaGetDriverEntryPoint("cuTensorMapEncodeTiled", &fp, cudaEnableDefault, &q);
        enc = (EncodeFn)fp;
    }

    CUtensorMap tmA, tmG;
    {   // hidden as 2D [B*S rows][H cols], box 8(h) x 128(s)
        cuuint64_t dims[2] = {HDIM, (cuuint64_t)BATCH * SLEN};
        cuuint64_t strides[1] = {HDIM * 4};
        cuuint32_t box[2] = {ROWS, TS};
        cuuint32_t es[2] = {1, 1};
        enc(&tmA, CU_TENSOR_MAP_DATA_TYPE_FLOAT32, 2, (void*)hidden,
            dims, strides, box, es,
            CU_TENSOR_MAP_INTERLEAVE_NONE, CU_TENSOR_MAP_SWIZZLE_NONE,
            CU_TENSOR_MAP_L2_PROMOTION_L2_128B, CU_TENSOR_MAP_FLOAT_OOB_FILL_NONE);
    }
    {   // gumbel as 2D [R rows][S cols], box 128(s) x 8(rows)
        cuuint64_t dims[2] = {SLEN, (cuuint64_t)BATCH * HDIM};
        cuuint64_t strides[1] = {SLEN * 4};
        cuuint32_t box[2] = {TS, ROWS};
        cuuint32_t es[2] = {1, 1};
        enc(&tmG, CU_TENSOR_MAP_DATA_TYPE_FLOAT32, 2, (void*)gumbel,
            dims, strides, box, es,
            CU_TENSOR_MAP_INTERLEAVE_NONE, CU_TENSOR_MAP_SWIZZLE_NONE,
            CU_TENSOR_MAP_L2_PROMOTION_L2_128B, CU_TENSOR_MAP_FLOAT_OOB_FILL_NONE);
    }

    topk_pool_kernel<<<BATCH * (HDIM / ROWS), 256>>>(tmA, tmG);
    gemm_tanh_kernel<<<HDIM / 4, 256>>>(W, bias, out);
}